// round 1
// baseline (speedup 1.0000x reference)
#include <cuda_runtime.h>

#define BDIM 2048
#define TDIM 128
#define FDIM 8
#define UO   128
#define UI   64
#define BT   16          // batch rows per CTA
#define NTHR 256
#define HP   18          // padded row stride (floats) for transposed h in smem
#define BN_EPS 1e-3f

// ---------------- folded-weight scratch (BN folded into consumer matmuls) ----
__device__ float g_Wk2f[UO * 4 * UI];   // 128 x 256
__device__ float g_b2f[4 * UI];
__device__ float g_Wk3f[UI * 4 * UI];   // 64 x 256
__device__ float g_b3f[4 * UI];
__device__ float g_Wk4f[UI * 4 * UO];   // 64 x 512
__device__ float g_b4f[4 * UO];
__device__ float g_Wdf[UO * FDIM];      // 128 x 8
__device__ float g_bdf[FDIM];

// ---------------- helpers ----------------------------------------------------
__device__ __forceinline__ float2 ffma2f(float2 a, float2 b, float2 c) {
    union U { float2 f; unsigned long long u; };
    U A, B, C, D;
    A.f = a; B.f = b; C.f = c;
    asm("fma.rn.f32x2 %0, %1, %2, %3;" : "=l"(D.u) : "l"(A.u), "l"(B.u), "l"(C.u));
    return D.f;
}

__device__ __forceinline__ float sigm(float x) { return 1.0f / (1.0f + __expf(-x)); }

__device__ __forceinline__ float seluf(float x) {
    const float l = 1.0507009873554805f;
    const float a = 1.6732632423543772f;
    return x > 0.0f ? l * x : l * a * (__expf(x) - 1.0f);
}

__device__ __forceinline__ void gate_update(float zi, float zf, float zg, float zo,
                                            float& c, float& h) {
    float i = sigm(zi), f = sigm(zf), g = seluf(zg), o = sigm(zo);
    c = f * c + i * g;
    h = o * seluf(c);
}

// acc[gate][rowpair] += h_pair * w[gate]  (w splat into both lanes)
template <int NP>
__device__ __forceinline__ void fma_step(float2 (&acc)[4][NP], const float* __restrict__ wp,
                                         int gstride, const float* __restrict__ hb) {
    float ww[4];
#pragma unroll
    for (int g = 0; g < 4; g++) ww[g] = __ldg(wp + g * gstride);
    float2 hh[NP];
#pragma unroll
    for (int p = 0; p < NP; p++) hh[p] = *(const float2*)(hb + 2 * p);
#pragma unroll
    for (int g = 0; g < 4; g++) {
        float2 W = make_float2(ww[g], ww[g]);
#pragma unroll
        for (int p = 0; p < NP; p++) acc[g][p] = ffma2f(hh[p], W, acc[g][p]);
    }
}

template <int NP>
__device__ __forceinline__ void init_acc(float2 (&acc)[4][NP], const float b[4]) {
#pragma unroll
    for (int g = 0; g < 4; g++)
#pragma unroll
        for (int p = 0; p < NP; p++) acc[g][p] = make_float2(b[g], b[g]);
}

template <int NP>
__device__ __forceinline__ void gates_write(float2 (&acc)[4][NP], float* cvec, float* hrow) {
#pragma unroll
    for (int p = 0; p < NP; p++) {
        {
            float c = cvec[2 * p], h;
            gate_update(acc[0][p].x, acc[1][p].x, acc[2][p].x, acc[3][p].x, c, h);
            cvec[2 * p] = c; hrow[2 * p] = h;
        }
        {
            float c = cvec[2 * p + 1], h;
            gate_update(acc[0][p].y, acc[1][p].y, acc[2][p].y, acc[3][p].y, c, h);
            cvec[2 * p + 1] = c; hrow[2 * p + 1] = h;
        }
    }
}

// ---------------- prep: fold BN scale/shift into downstream weights ----------
__global__ void prep_kernel(
    const float* __restrict__ Wk2, const float* __restrict__ b2,
    const float* __restrict__ g1, const float* __restrict__ be1,
    const float* __restrict__ m1, const float* __restrict__ v1,
    const float* __restrict__ Wk3, const float* __restrict__ b3,
    const float* __restrict__ g2, const float* __restrict__ be2,
    const float* __restrict__ m2, const float* __restrict__ v2,
    const float* __restrict__ Wk4, const float* __restrict__ b4,
    const float* __restrict__ g3, const float* __restrict__ be3,
    const float* __restrict__ m3, const float* __restrict__ v3,
    const float* __restrict__ Wd, const float* __restrict__ bd,
    const float* __restrict__ g4, const float* __restrict__ be4,
    const float* __restrict__ m4, const float* __restrict__ v4) {
    int cid = blockIdx.x * blockDim.x + threadIdx.x;
    if (cid < 256) {                       // Wk2f: K=128, BN1 folded
        int c = cid;
        float acc = b2[c];
        for (int k = 0; k < 128; k++) {
            float s = g1[k] * rsqrtf(v1[k] + BN_EPS);
            float sh = be1[k] - m1[k] * s;
            float w = Wk2[k * 256 + c];
            g_Wk2f[k * 256 + c] = s * w;
            acc += sh * w;
        }
        g_b2f[c] = acc;
    } else if (cid < 512) {                // Wk3f: K=64, BN2 folded
        int c = cid - 256;
        float acc = b3[c];
        for (int k = 0; k < 64; k++) {
            float s = g2[k] * rsqrtf(v2[k] + BN_EPS);
            float sh = be2[k] - m2[k] * s;
            float w = Wk3[k * 256 + c];
            g_Wk3f[k * 256 + c] = s * w;
            acc += sh * w;
        }
        g_b3f[c] = acc;
    } else if (cid < 1024) {               // Wk4f: K=64, BN3 folded
        int c = cid - 512;
        float acc = b4[c];
        for (int k = 0; k < 64; k++) {
            float s = g3[k] * rsqrtf(v3[k] + BN_EPS);
            float sh = be3[k] - m3[k] * s;
            float w = Wk4[k * 512 + c];
            g_Wk4f[k * 512 + c] = s * w;
            acc += sh * w;
        }
        g_b4f[c] = acc;
    } else if (cid < 1024 + FDIM) {        // Wdf: K=128, BN4 folded
        int c = cid - 1024;
        float acc = bd[c];
        for (int k = 0; k < 128; k++) {
            float s = g4[k] * rsqrtf(v4[k] + BN_EPS);
            float sh = be4[k] - m4[k] * s;
            float w = Wd[k * FDIM + c];
            g_Wdf[k * FDIM + c] = s * w;
            acc += sh * w;
        }
        g_bdf[c] = acc;
    }
}

// ---------------- main: full autoencoder, one CTA per 16 batch rows ----------
__global__ __launch_bounds__(NTHR, 1)
void lstm_ae_kernel(const float* __restrict__ x,
                    const float* __restrict__ Wk1, const float* __restrict__ Wr1,
                    const float* __restrict__ b1,
                    const float* __restrict__ Wr2,
                    const float* __restrict__ Wr3,
                    const float* __restrict__ Wr4,
                    float* __restrict__ out) {
    __shared__ float h1s[UO * HP];
    __shared__ float h2s[UI * HP];
    __shared__ float h3s[UI * HP];
    __shared__ float h4s[UO * HP];
    __shared__ float xs[FDIM * HP];
    __shared__ float wds[UO * FDIM];
    __shared__ float bds[FDIM];

    const int tid  = threadIdx.x;
    const int row0 = blockIdx.x * BT;

    // big mapping (512-col GEMMs: z1 / z4): gate-quad u, 8 rows
    const int ub = tid & 127;
    const int rb = (tid >> 7) * 8;
    // small mapping (256-col GEMMs: z2 / z3): gate-quad u, 4 rows
    const int us = tid & 63;
    const int rs = (tid >> 6) * 4;

    for (int i = tid; i < UO * HP; i += NTHR) { h1s[i] = 0.f; h4s[i] = 0.f; }
    for (int i = tid; i < UI * HP; i += NTHR) { h2s[i] = 0.f; h3s[i] = 0.f; }
    for (int i = tid; i < UO * FDIM; i += NTHR) wds[i] = g_Wdf[i];
    if (tid < FDIM) bds[tid] = g_bdf[tid];
    if (tid < BT * FDIM) {
        int r = tid >> 3, k = tid & 7;
        xs[k * HP + r] = x[(size_t)(row0 + r) * TDIM * FDIM + k];
    }

    float bb1[4], bb2[4], bb4[4];
#pragma unroll
    for (int g = 0; g < 4; g++) {
        bb1[g] = b1[g * UO + ub];
        bb2[g] = g_b2f[g * UI + us];
        bb4[g] = g_b4f[g * UO + ub];
    }

    float c1v[8], c4v[8];
    float c2v[4], c3v[4];
#pragma unroll
    for (int i = 0; i < 8; i++) { c1v[i] = 0.f; c4v[i] = 0.f; }
#pragma unroll
    for (int i = 0; i < 4; i++) { c2v[i] = 0.f; c3v[i] = 0.f; }

    __syncthreads();

    // ================= Phase A: encoder (LSTM1 -> BN1 -> LSTM2) ==============
    for (int t = 0; t < TDIM; t++) {
        // z1 = x_t@Wk1 + b1 + h1@Wr1   (reads h1s OLD)
        float2 a1[4][4];
        init_acc<4>(a1, bb1);
#pragma unroll
        for (int k = 0; k < FDIM; k++)
            fma_step<4>(a1, Wk1 + k * 4 * UO + ub, UO, xs + k * HP + rb);
#pragma unroll 4
        for (int k = 0; k < UO; k++)
            fma_step<4>(a1, Wr1 + k * 4 * UO + ub, UO, h1s + k * HP + rb);

        // z2 recurrent part = h2@Wr2   (reads h2s OLD)
        float2 a2[4][2];
        init_acc<2>(a2, bb2);
#pragma unroll 4
        for (int k = 0; k < UI; k++)
            fma_step<2>(a2, Wr2 + k * 4 * UI + us, UI, h2s + k * HP + rs);

        __syncthreads();  // all old-state reads complete

        gates_write<4>(a1, c1v, h1s + ub * HP + rb);   // write h1 NEW
        if (t + 1 < TDIM && tid < BT * FDIM) {         // prefetch x_{t+1}
            int r = tid >> 3, k = tid & 7;
            xs[k * HP + r] = x[(size_t)(row0 + r) * TDIM * FDIM + (t + 1) * FDIM + k];
        }
        __syncthreads();  // h1 NEW visible

        // z2 input part = h1_new @ Wk2f (BN1 folded)
#pragma unroll 4
        for (int k = 0; k < UO; k++)
            fma_step<2>(a2, g_Wk2f + k * 4 * UI + us, UI, h1s + k * HP + rs);

        gates_write<2>(a2, c2v, h2s + us * HP + rs);   // write h2 NEW
        __syncthreads();
    }

    // =============== transition: xz3 = enc_bn @ Wk3f + b3f (constant over t) ==
    float2 x3[4][2];
    {
        float bb3[4];
#pragma unroll
        for (int g = 0; g < 4; g++) bb3[g] = g_b3f[g * UI + us];
        init_acc<2>(x3, bb3);
#pragma unroll 4
        for (int k = 0; k < UI; k++)
            fma_step<2>(x3, g_Wk3f + k * 4 * UI + us, UI, h2s + k * HP + rs);
    }

    // ================= Phase B: decoder (LSTM3 -> BN3 -> LSTM4 -> BN4 -> Dense)
    const int dr = tid >> 3, dc = tid & 7;  // dense mapping (tid < 128)
    for (int t = 0; t < TDIM; t++) {
        // z3 = xz3 + h3@Wr3  (reads h3s OLD)
        float2 a3[4][2];
#pragma unroll
        for (int g = 0; g < 4; g++)
#pragma unroll
            for (int p = 0; p < 2; p++) a3[g][p] = x3[g][p];
#pragma unroll 4
        for (int k = 0; k < UI; k++)
            fma_step<2>(a3, Wr3 + k * 4 * UI + us, UI, h3s + k * HP + rs);

        // z4 recurrent part = h4@Wr4  (reads h4s OLD)
        float2 a4[4][4];
        init_acc<4>(a4, bb4);
#pragma unroll 4
        for (int k = 0; k < UO; k++)
            fma_step<4>(a4, Wr4 + k * 4 * UO + ub, UO, h4s + k * HP + rb);

        __syncthreads();  // all old-state reads complete

        gates_write<2>(a3, c3v, h3s + us * HP + rs);   // write h3 NEW
        __syncthreads();  // h3 NEW visible

        // z4 input part = h3_new @ Wk4f (BN3 folded)
#pragma unroll 4
        for (int k = 0; k < UI; k++)
            fma_step<4>(a4, g_Wk4f + k * 4 * UO + ub, UO, h3s + k * HP + rb);

        gates_write<4>(a4, c4v, h4s + ub * HP + rb);   // write h4 NEW
        __syncthreads();  // h4 NEW visible

        // dense head (BN4 folded): out[:, t, :] = h4_new @ Wdf + bdf
        if (tid < BT * FDIM) {
            float acc = bds[dc];
#pragma unroll 8
            for (int k = 0; k < UO; k++) acc += h4s[k * HP + dr] * wds[k * FDIM + dc];
            out[(size_t)(row0 + dr) * TDIM * FDIM + t * FDIM + dc] = acc;
        }
    }
}

// ---------------- launch ------------------------------------------------------
extern "C" void kernel_launch(void* const* d_in, const int* in_sizes, int n_in,
                              void* d_out, int out_size) {
    const float* x   = (const float*)d_in[0];
    const float* Wk1 = (const float*)d_in[1];
    const float* Wr1 = (const float*)d_in[2];
    const float* b1  = (const float*)d_in[3];
    const float* g1  = (const float*)d_in[4];
    const float* be1 = (const float*)d_in[5];
    const float* m1  = (const float*)d_in[6];
    const float* v1  = (const float*)d_in[7];
    const float* Wk2 = (const float*)d_in[8];
    const float* Wr2 = (const float*)d_in[9];
    const float* b2  = (const float*)d_in[10];
    const float* g2  = (const float*)d_in[11];
    const float* be2 = (const float*)d_in[12];
    const float* m2  = (const float*)d_in[13];
    const float* v2  = (const float*)d_in[14];
    const float* Wk3 = (const float*)d_in[15];
    const float* Wr3 = (const float*)d_in[16];
    const float* b3  = (const float*)d_in[17];
    const float* g3  = (const float*)d_in[18];
    const float* be3 = (const float*)d_in[19];
    const float* m3  = (const float*)d_in[20];
    const float* v3  = (const float*)d_in[21];
    const float* Wk4 = (const float*)d_in[22];
    const float* Wr4 = (const float*)d_in[23];
    const float* b4  = (const float*)d_in[24];
    const float* g4  = (const float*)d_in[25];
    const float* be4 = (const float*)d_in[26];
    const float* m4  = (const float*)d_in[27];
    const float* v4  = (const float*)d_in[28];
    const float* Wd  = (const float*)d_in[29];
    const float* bd  = (const float*)d_in[30];

    prep_kernel<<<5, 256>>>(Wk2, b2, g1, be1, m1, v1,
                            Wk3, b3, g2, be2, m2, v2,
                            Wk4, b4, g3, be3, m3, v3,
                            Wd,  bd, g4, be4, m4, v4);
    lstm_ae_kernel<<<BDIM / BT, NTHR>>>(x, Wk1, Wr1, b1, Wr2, Wr3, Wr4, (float*)d_out);
}